// round 16
// baseline (speedup 1.0000x reference)
#include <cuda_runtime.h>
#include <cuda_bf16.h>
#include <math.h>
#include <float.h>

// ---------------------------------------------------------------------------
// Self_Correlation_Per_tt : x[8,64,64,64] fp32 -> out[8,115,24,24] fp32
// s1a: per (b,c,di) lag sliding sums (rows straight from global) -> G scatter.
// s1b: norms + warp-sort ranking.  stage2: fused norms+dot+576 bitonic sort.
// ---------------------------------------------------------------------------

#define CMS 65          // s_corr stride
#define RMS 121         // R row stride
#define NP 3249         // 57*57 patch positions
#define POOL_P 576      // 9*64
#define OUT_R 115

#define S1A_SMEM_BYTES (64 * RMS * 4)

__device__ __align__(16) float g_corr[512 * 4096];          // [bc][m*64+n]
__device__ __align__(16) float g_pool2t[8 * 64 * POOL_P];   // [b][c][p]

// XOR bank swizzle
__device__ __forceinline__ int ph(int i) {
    return (i & ~31) | ((i ^ (i >> 5)) & 31);
}

// ---------------------------------------------------------------------------
// Stage 1a: one block per (bc, di). 128 threads = 64 rows x 2 halves.
// Rows loaded directly from global (coalesced); smem holds only R.
// ---------------------------------------------------------------------------
__global__ __launch_bounds__(128) void s1a_kernel(const float* __restrict__ x)
{
    extern __shared__ float s_R[];     // [64][RMS]

    const int tid = threadIdx.x;
    const int blk = blockIdx.x;
    const int bc  = blk >> 3;
    const int di  = blk & 7;

    const float* src = x + (size_t)bc * 4096;

    const int u = tid >> 1;            // image row
    const int h = tid & 1;             // v-half
    const bool act = (u + di <= 63);
    const int rowB = act ? (u + di) : 63;

    float ra[32];
    {
        const float4* pA = (const float4*)(src + u * 64 + h * 32);
#pragma unroll
        for (int t = 0; t < 8; ++t) {
            float4 v = pA[t];
            ra[4*t+0] = v.x; ra[4*t+1] = v.y; ra[4*t+2] = v.z; ra[4*t+3] = v.w;
        }
    }
    // rbx: zero-padded window of row u+di:
    //   h=0: rbx[idx] = col (idx-7)   (cols -7..40; <0 zeroed)
    //   h=1: rbx[idx] = col (idx+25)  (cols 25..72; >63 zeroed)
    float rbx[48];
#pragma unroll
    for (int i = 0; i < 48; ++i) rbx[i] = 0.0f;
    if (h == 0) {
        const float4* pB = (const float4*)(src + rowB * 64);
#pragma unroll
        for (int t = 0; t < 10; ++t) {
            float4 v = pB[t];
            rbx[7+4*t] = v.x; rbx[8+4*t] = v.y;
            rbx[9+4*t] = v.z; rbx[10+4*t] = v.w;
        }
    } else {
        const float4* pB = (const float4*)(src + rowB * 64 + 24);
        {
            float4 v = pB[0];                 // cols 24..27 -> idx -1..2
            rbx[0] = v.y; rbx[1] = v.z; rbx[2] = v.w;
        }
#pragma unroll
        for (int t = 1; t < 10; ++t) {
            float4 v = pB[t];                 // cols 24+4t -> idx 4t-1
            rbx[4*t-1] = v.x; rbx[4*t+0] = v.y;
            rbx[4*t+1] = v.z; rbx[4*t+2] = v.w;
        }
    }

    float* Rrow = s_R + u * RMS;

#pragma unroll
    for (int dj = -7; dj <= 7; ++dj) {
        const int bl = (dj < 0) ? -dj : 0;
        const int bh = (dj > 0) ? 7 - dj : 7;

        float ac0 = 0.f, ac1 = 0.f, ac2 = 0.f, ac3 = 0.f;
#pragma unroll
        for (int w2 = 0; w2 < 32; w2 += 4) {
            ac0 = fmaf(ra[w2+0], rbx[w2+dj+7],  ac0);
            ac1 = fmaf(ra[w2+1], rbx[w2+dj+8],  ac1);
            ac2 = fmaf(ra[w2+2], rbx[w2+dj+9],  ac2);
            ac3 = fmaf(ra[w2+3], rbx[w2+dj+10], ac3);
        }
        const float base = (ac0 + ac2) + (ac1 + ac3);

        float part[8];
        if (h == 0) {
            part[0] = base;
#pragma unroll
            for (int k = 1; k <= 7; ++k)
                part[k] = part[k-1] - ra[k-1] * rbx[k-1+dj+7];
        } else {
            part[7] = base;
#pragma unroll
            for (int k = 6; k >= 0; --k)
                part[k] = part[k+1] - ra[k+25] * rbx[k+dj+32];
        }

#pragma unroll
        for (int k = bl; k <= bh; ++k) {
            float Rv = part[k] + __shfl_xor_sync(0xffffffffu, part[k], 1);
            if (h == 0 && act)
                Rrow[(dj + 7) * 8 + k] = Rv;
        }
    }
    __syncthreads();

    if (tid < 120) {
        const int dj = tid / 8 - 7;
        const int b2 = tid % 8;
        const int bl = (dj < 0) ? -dj : 0;
        const int bh = (dj > 0) ? 7 - dj : 7;
        if (b2 >= bl && b2 <= bh && !(di == 0 && dj < 0)) {
            const float* Rcol = s_R + tid;
            float a0 = 0.f, a1 = 0.f, a2 = 0.f, a3 = 0.f;
#pragma unroll
            for (int uu = 0; uu < 56; uu += 4) {
                a0 += Rcol[(uu    ) * RMS];
                a1 += Rcol[(uu + 1) * RMS];
                a2 += Rcol[(uu + 2) * RMS];
                a3 += Rcol[(uu + 3) * RMS];
            }
            float acc = ((a0 + a2) + (a1 + a3)) + Rcol[56 * RMS];
            float* gc = g_corr + (size_t)bc * 4096;
            int m = b2;
            int n = di * 8 + (b2 + dj);
            gc[m * 64 + n] = acc;
            gc[n * 64 + m] = acc;
#pragma unroll
            for (int a = 1; a <= 7; ++a) {
                if (a <= 7 - di) {
                    acc += Rcol[(a + 56) * RMS] - Rcol[(a - 1) * RMS];
                    m = a * 8 + b2;
                    n = (a + di) * 8 + (b2 + dj);
                    gc[m * 64 + n] = acc;
                    gc[n * 64 + m] = acc;
                }
            }
        }
    }
}

// ---------------------------------------------------------------------------
// Stage 1b: one block per bc. Norms + warp-sort ranking -> pool (c-major).
// ---------------------------------------------------------------------------
__global__ __launch_bounds__(256) void s1b_kernel()
{
    __shared__ float s_corr[64 * CMS];
    __shared__ float s_norm[64];

    const int tid = threadIdx.x;
    const int bc  = blockIdx.x;
    const int bb  = bc >> 6;
    const int cc  = bc & 63;

    const float* src = g_corr + (size_t)bc * 4096;
    for (int i = tid; i < 4096; i += 256)
        s_corr[(i >> 6) * CMS + (i & 63)] = src[i];
    __syncthreads();

    if (tid < 64) {
        float gdiag = s_corr[tid * CMS + tid];
        s_norm[tid] = 1.0f / fmaxf(sqrtf(gdiag), 1e-12f);
    }
    __syncthreads();

    const int lane = tid & 31;
    const int w    = tid >> 5;
    float* dstc = g_pool2t + (size_t)(bb * 64 + cc) * POOL_P;
    const float invP = 1.0f / (float)NP;
    const float nm0 = s_norm[lane] * invP;
    const float nm1 = s_norm[lane + 32] * invP;

    float v0[8], v1[8];
#pragma unroll
    for (int ci = 0; ci < 8; ++ci) {
        const int n = w * 8 + ci;
        const float sn = s_norm[n];
        v0[ci] = s_corr[lane * CMS + n] * nm0 * sn;
        v1[ci] = s_corr[(lane + 32) * CMS + n] * nm1 * sn;
    }

#pragma unroll
    for (int s = 1; s <= 5; ++s) {
        const int kk = 1 << s;
#pragma unroll
        for (int j = (1 << (s - 1)); j >= 1; j >>= 1) {
#pragma unroll
            for (int ci = 0; ci < 8; ++ci) {
                const bool A = ((lane & j) == 0);
                bool d0, d1;
                if (s < 5) { d0 = ((lane & kk) == 0); d1 = d0; }
                else       { d0 = true; d1 = false; }
                float p0 = __shfl_xor_sync(0xffffffffu, v0[ci], j);
                v0[ci] = ((d0 == A) ? fmaxf(v0[ci], p0) : fminf(v0[ci], p0));
                float p1 = __shfl_xor_sync(0xffffffffu, v1[ci], j);
                v1[ci] = ((d1 == A) ? fmaxf(v1[ci], p1) : fminf(v1[ci], p1));
            }
        }
    }
#pragma unroll
    for (int ci = 0; ci < 8; ++ci) {
        float hi = fmaxf(v0[ci], v1[ci]);
        float lo = fminf(v0[ci], v1[ci]);
        v0[ci] = hi; v1[ci] = lo;
    }
#pragma unroll
    for (int j = 16; j >= 1; j >>= 1) {
#pragma unroll
        for (int ci = 0; ci < 8; ++ci) {
            const bool A = ((lane & j) == 0);
            float p0 = __shfl_xor_sync(0xffffffffu, v0[ci], j);
            v0[ci] = A ? fmaxf(v0[ci], p0) : fminf(v0[ci], p0);
            float p1 = __shfl_xor_sync(0xffffffffu, v1[ci], j);
            v1[ci] = A ? fmaxf(v1[ci], p1) : fminf(v1[ci], p1);
        }
    }

#pragma unroll
    for (int ci = 0; ci < 8; ++ci) {
        const int n = w * 8 + ci;
        if (lane == 1)  dstc[0 * 64 + n] = v0[ci];
        if (lane == 9)  dstc[1 * 64 + n] = v0[ci];
        if (lane == 16) dstc[2 * 64 + n] = v0[ci];
        if (lane == 24) dstc[3 * 64 + n] = v0[ci];
        if (lane == 0)  dstc[4 * 64 + n] = v1[ci];
        if (lane == 8)  dstc[5 * 64 + n] = v1[ci];
        if (lane == 16) dstc[6 * 64 + n] = v1[ci];
        if (lane == 23) dstc[7 * 64 + n] = v1[ci];
        if (lane == 31) dstc[8 * 64 + n] = v1[ci];
    }
}

// ---------------------------------------------------------------------------
// Sort primitives (r-major layout i = r*32 + lane, regs 0..17 all real).
// ---------------------------------------------------------------------------
__device__ __forceinline__ void sh(float& v, int j, bool keep_max) {
    float pv = __shfl_xor_sync(0xffffffffu, v, j);
    v = keep_max ? fmaxf(v, pv) : fminf(v, pv);
}
__device__ __forceinline__ void cx(float& a, float& b, bool dsc) {
    float x = a, y = b;
    a = dsc ? fmaxf(x, y) : fminf(x, y);
    b = dsc ? fminf(x, y) : fmaxf(x, y);
}

// ---------------------------------------------------------------------------
// Stage 2 (fused): one block per (b, 8 q). Dot phase computes per-p inverse
// norms inline; warp w sorts column q0+w with the dummy-free 576 network.
// ---------------------------------------------------------------------------
__global__ __launch_bounds__(256, 4) void stage2_kernel(float* __restrict__ out)
{
    __shared__ float4 s_xq4[8][16];          // 8 q vectors x 64 ch
    __shared__ float  s_cols[8][POOL_P];     // swizzled via ph()
    __shared__ float  s_ip[POOL_P];          // inverse norms

    const int tid  = threadIdx.x;
    const int lane = tid & 31;
    const int w    = tid >> 5;
    const int b    = blockIdx.x / 72;
    const int q0   = (blockIdx.x % 72) * 8;

    const float* poolb = g_pool2t + (size_t)b * 64 * POOL_P;

    {   // load 8 q vectors
        float* sx = (float*)s_xq4;
        for (int i = tid; i < 512; i += 256) {
            int k = i >> 6, c = i & 63;
            sx[k * 64 + c] = poolb[(size_t)c * POOL_P + (q0 + k)];
        }
    }
    __syncthreads();

    // ---- dot phase + inline norms -----------------------------------------
#pragma unroll
    for (int pi = 0; pi < 3; ++pi) {
        const int p = tid + pi * 256;
        if (p < POOL_P) {
            float d[8];
#pragma unroll
            for (int k = 0; k < 8; ++k) d[k] = 0.0f;
            float n0 = 0.f, n1 = 0.f, n2 = 0.f, n3 = 0.f;
#pragma unroll 4
            for (int c4 = 0; c4 < 16; ++c4) {
                const float* xb = poolb + (size_t)(c4 * 4) * POOL_P + p;
                float x0 = xb[0];
                float x1 = xb[POOL_P];
                float x2 = xb[2 * POOL_P];
                float x3 = xb[3 * POOL_P];
                n0 = fmaf(x0, x0, n0); n1 = fmaf(x1, x1, n1);
                n2 = fmaf(x2, x2, n2); n3 = fmaf(x3, x3, n3);
#pragma unroll
                for (int k = 0; k < 8; ++k) {
                    float4 q = s_xq4[k][c4];
                    d[k] = fmaf(x0, q.x, d[k]);
                    d[k] = fmaf(x1, q.y, d[k]);
                    d[k] = fmaf(x2, q.z, d[k]);
                    d[k] = fmaf(x3, q.w, d[k]);
                }
            }
            const float s = (n0 + n2) + (n1 + n3);
            const float ip = 1.0f / fmaxf(sqrtf(s), 1e-12f);
            s_ip[p] = ip;
            const int pp = ph(p);
#pragma unroll
            for (int k = 0; k < 8; ++k)
                s_cols[k][pp] = d[k] * ip;
        }
    }
    __syncthreads();

    // ---- dummy-free 576 bitonic sort, i = r*32 + lane (r = 0..17) ---------
    {
        float v[18];
#pragma unroll
        for (int r = 0; r < 18; ++r)
            v[r] = s_cols[w][r * 32 + ((lane ^ r) & 31)];

        // stages 1..4
#pragma unroll
        for (int s = 1; s <= 4; ++s) {
            const int kk = 1 << s;
#pragma unroll
            for (int j = kk >> 1; j >= 1; j >>= 1) {
                const bool km = (((lane & kk) == 0) == ((lane & j) == 0));
#pragma unroll
                for (int r = 0; r < 18; ++r) sh(v[r], j, km);
            }
        }
        // stage 5
#pragma unroll
        for (int j = 16; j >= 1; j >>= 1) {
            const bool A = (lane & j) == 0;
#pragma unroll
            for (int r = 0; r < 18; ++r) sh(v[r], j, ((r & 1) == 0) == A);
        }
        // stage 6
#pragma unroll
        for (int m = 0; m < 9; ++m) cx(v[2*m], v[2*m+1], (m & 1) == 0);
#pragma unroll
        for (int j = 16; j >= 1; j >>= 1) {
            const bool A = (lane & j) == 0;
#pragma unroll
            for (int r = 0; r < 18; ++r) sh(v[r], j, ((r & 2) == 0) == A);
        }
        // stage 7
#pragma unroll
        for (int g = 0; g < 4; ++g) {
            cx(v[4*g],   v[4*g+2], (g & 1) == 0);
            cx(v[4*g+1], v[4*g+3], (g & 1) == 0);
        }
#pragma unroll
        for (int m = 0; m < 9; ++m) cx(v[2*m], v[2*m+1], (m & 2) == 0);
#pragma unroll
        for (int j = 16; j >= 1; j >>= 1) {
            const bool A = (lane & j) == 0;
#pragma unroll
            for (int r = 0; r < 18; ++r) sh(v[r], j, ((r & 4) == 0) == A);
        }
        // stage 8
#pragma unroll
        for (int g = 0; g < 2; ++g)
#pragma unroll
            for (int t = 0; t < 4; ++t)
                cx(v[8*g + t], v[8*g + t + 4], g == 0);
#pragma unroll
        for (int g = 0; g < 4; ++g) {
            const bool d8 = ((4 * g) & 8) == 0;
            cx(v[4*g],   v[4*g+2], d8);
            cx(v[4*g+1], v[4*g+3], d8);
        }
#pragma unroll
        for (int m = 0; m < 9; ++m) cx(v[2*m], v[2*m+1], (m & 4) == 0);
#pragma unroll
        for (int j = 16; j >= 1; j >>= 1) {
            const bool A = (lane & j) == 0;
#pragma unroll
            for (int r = 0; r < 18; ++r) sh(v[r], j, ((r & 8) == 0) == A);
        }
        // stage 9
        float ua = __shfl_xor_sync(0xffffffffu, v[17], 31);   // role 30
        float ub = __shfl_xor_sync(0xffffffffu, v[16], 31);   // role 31
#pragma unroll
        for (int r = 0; r < 8; ++r) cx(v[r], v[r+8], true);
#pragma unroll
        for (int g = 0; g < 2; ++g)
#pragma unroll
            for (int t = 0; t < 4; ++t) cx(v[8*g+t], v[8*g+t+4], true);
#pragma unroll
        for (int g = 0; g < 4; ++g) { cx(v[4*g], v[4*g+2], true); cx(v[4*g+1], v[4*g+3], true); }
#pragma unroll
        for (int m = 0; m < 8; ++m) cx(v[2*m], v[2*m+1], true);
#pragma unroll
        for (int j = 16; j >= 1; j >>= 1) {
            const bool A = (lane & j) == 0;
#pragma unroll
            for (int r = 0; r < 16; ++r) sh(v[r], j, A);
        }
        // stage 10
        cx(v[14], ua, true);
        cx(v[15], ub, true);
#pragma unroll
        for (int r = 0; r < 8; ++r) cx(v[r], v[r+8], true);
#pragma unroll
        for (int g = 0; g < 2; ++g)
#pragma unroll
            for (int t = 0; t < 4; ++t) cx(v[8*g+t], v[8*g+t+4], true);
#pragma unroll
        for (int g = 0; g < 4; ++g) { cx(v[4*g], v[4*g+2], true); cx(v[4*g+1], v[4*g+3], true); }
#pragma unroll
        for (int m = 0; m < 8; ++m) cx(v[2*m], v[2*m+1], true);
#pragma unroll
        for (int j = 16; j >= 1; j >>= 1) {
            const bool A = (lane & j) == 0;
#pragma unroll
            for (int r = 0; r < 16; ++r) sh(v[r], j, A);
        }
        cx(ua, ub, true);
#pragma unroll
        for (int j = 16; j >= 1; j >>= 1) {
            const bool A = (lane & j) == 0;
            sh(ua, j, A);
            sh(ub, j, A);
        }
        v[16] = ua; v[17] = ub;

#pragma unroll
        for (int r = 0; r < 18; ++r)
            s_cols[w][r * 32 + ((lane ^ r) & 31)] = v[r];
    }
    __syncthreads();

    const double step = 574.0 / 114.0;   // np.linspace(1, 575, 115) step
    for (int idx = tid; idx < 8 * OUT_R; idx += 256) {
        int k = idx & 7, rr = idx >> 3;
        int rank = (int)rint(1.0 + (double)rr * step);  // half-even == np.round
        float invq = s_ip[q0 + k];
        out[((size_t)b * OUT_R + rr) * POOL_P + (q0 + k)] =
            s_cols[k][ph(rank)] * invq * (1.0f / 64.0f);
    }
}

// ---------------------------------------------------------------------------
extern "C" void kernel_launch(void* const* d_in, const int* in_sizes, int n_in,
                              void* d_out, int out_size)
{
    const float* x = (const float*)d_in[0];
    float* out = (float*)d_out;

    s1a_kernel<<<512 * 8, 128, S1A_SMEM_BYTES>>>(x);
    s1b_kernel<<<512, 256>>>();
    stage2_kernel<<<8 * 72, 256>>>(out);
}

// round 17
// speedup vs baseline: 1.1384x; 1.1384x over previous
#include <cuda_runtime.h>
#include <cuda_bf16.h>
#include <math.h>
#include <float.h>

// ---------------------------------------------------------------------------
// Self_Correlation_Per_tt : x[8,64,64,64] fp32 -> out[8,115,24,24] fp32
// s1a: per (b,c,di) lag sliding sums, COMPACT R (64 valid (dj,k) columns).
// s1b: norms + warp-sort ranking.  stage2: fused norms+dot+576 bitonic sort.
// ---------------------------------------------------------------------------

#define IMS 68          // s_img stride
#define CMS 65          // s_corr stride
#define RMS 65          // compact R row stride (64 cols + 1 pad)
#define NP 3249         // 57*57 patch positions
#define POOL_P 576      // 9*64
#define OUT_R 115

#define S1A_SMEM_FLOATS (64 * IMS + 64 * RMS)
#define S1A_SMEM_BYTES  (S1A_SMEM_FLOATS * 4)

__device__ __align__(16) float g_corr[512 * 4096];          // [bc][m*64+n]
__device__ __align__(16) float g_pool2t[8 * 64 * POOL_P];   // [b][c][p]

// phase-B task tables: compact column t -> (dj, b2)
__constant__ signed char c_dj[64] = {
    -7, -6,-6, -5,-5,-5, -4,-4,-4,-4, -3,-3,-3,-3,-3,
    -2,-2,-2,-2,-2,-2, -1,-1,-1,-1,-1,-1,-1,
     0, 0, 0, 0, 0, 0, 0, 0,
     1, 1, 1, 1, 1, 1, 1,  2, 2, 2, 2, 2, 2,
     3, 3, 3, 3, 3,  4, 4, 4, 4,  5, 5, 5,  6, 6,  7 };
__constant__ signed char c_b2[64] = {
     7, 6, 7, 5, 6, 7, 4, 5, 6, 7, 3, 4, 5, 6, 7,
     2, 3, 4, 5, 6, 7, 1, 2, 3, 4, 5, 6, 7,
     0, 1, 2, 3, 4, 5, 6, 7,
     0, 1, 2, 3, 4, 5, 6,  0, 1, 2, 3, 4, 5,
     0, 1, 2, 3, 4,  0, 1, 2, 3,  0, 1, 2,  0, 1,  0 };

// XOR bank swizzle
__device__ __forceinline__ int ph(int i) {
    return (i & ~31) | ((i ^ (i >> 5)) & 31);
}

// ---------------------------------------------------------------------------
// Stage 1a: one block per (bc, di). 128 threads = 64 rows x 2 halves.
// ---------------------------------------------------------------------------
__global__ __launch_bounds__(128) void s1a_kernel(const float* __restrict__ x)
{
    extern __shared__ float smem[];
    float* s_img = smem;               // [64][IMS]
    float* s_R   = smem + 64 * IMS;    // [64][RMS] compact

    const int tid = threadIdx.x;
    const int blk = blockIdx.x;
    const int bc  = blk >> 3;
    const int di  = blk & 7;

    const float* src = x + (size_t)bc * 4096;
    for (int i = tid; i < 4096; i += 128)
        s_img[(i >> 6) * IMS + (i & 63)] = src[i];
    __syncthreads();

    const int u = tid >> 1;            // image row
    const int h = tid & 1;             // v-half
    const bool act = (u + di <= 63);
    const int rowB = act ? (u + di) : 63;

    float ra[32];
    {
        const float4* pA = (const float4*)(s_img + u * IMS + h * 32);
#pragma unroll
        for (int t = 0; t < 8; ++t) {
            float4 v = pA[t];
            ra[4*t+0] = v.x; ra[4*t+1] = v.y; ra[4*t+2] = v.z; ra[4*t+3] = v.w;
        }
    }
    float rbx[48];
#pragma unroll
    for (int i = 0; i < 48; ++i) rbx[i] = 0.0f;
    if (h == 0) {
        const float4* pB = (const float4*)(s_img + rowB * IMS);
#pragma unroll
        for (int t = 0; t < 10; ++t) {
            float4 v = pB[t];
            rbx[7+4*t] = v.x; rbx[8+4*t] = v.y;
            rbx[9+4*t] = v.z; rbx[10+4*t] = v.w;
        }
    } else {
        const float4* pB = (const float4*)(s_img + rowB * IMS + 24);
        {
            float4 v = pB[0];
            rbx[0] = v.y; rbx[1] = v.z; rbx[2] = v.w;
        }
#pragma unroll
        for (int t = 1; t < 10; ++t) {
            float4 v = pB[t];
            rbx[4*t-1] = v.x; rbx[4*t+0] = v.y;
            rbx[4*t+1] = v.z; rbx[4*t+2] = v.w;
        }
    }

    float* Rrow = s_R + u * RMS;

#pragma unroll
    for (int dj = -7; dj <= 7; ++dj) {
        const int bl = (dj < 0) ? -dj : 0;
        const int bh = (dj > 0) ? 7 - dj : 7;
        // compact column offset (constant-folded: dj is compile-time)
        const int coff = (dj <= 0) ? ((dj + 7) * (dj + 8)) / 2
                                   : 36 + (dj - 1) * 8 - ((dj - 1) * dj) / 2;

        float ac0 = 0.f, ac1 = 0.f, ac2 = 0.f, ac3 = 0.f;
#pragma unroll
        for (int w2 = 0; w2 < 32; w2 += 4) {
            ac0 = fmaf(ra[w2+0], rbx[w2+dj+7],  ac0);
            ac1 = fmaf(ra[w2+1], rbx[w2+dj+8],  ac1);
            ac2 = fmaf(ra[w2+2], rbx[w2+dj+9],  ac2);
            ac3 = fmaf(ra[w2+3], rbx[w2+dj+10], ac3);
        }
        const float base = (ac0 + ac2) + (ac1 + ac3);

        float part[8];
        if (h == 0) {
            part[0] = base;
#pragma unroll
            for (int k = 1; k <= 7; ++k)
                part[k] = part[k-1] - ra[k-1] * rbx[k-1+dj+7];
        } else {
            part[7] = base;
#pragma unroll
            for (int k = 6; k >= 0; --k)
                part[k] = part[k+1] - ra[k+25] * rbx[k+dj+32];
        }

#pragma unroll
        for (int k = bl; k <= bh; ++k) {
            float Rv = part[k] + __shfl_xor_sync(0xffffffffu, part[k], 1);
            if (h == 0 && act)
                Rrow[coff + (k - bl)] = Rv;
        }
    }
    __syncthreads();

    // ---- phase B: 64 compact tasks, one per thread (tid < 64) -------------
    if (tid < 64) {
        const int dj = c_dj[tid];
        const int b2 = c_b2[tid];
        if (!(di == 0 && dj < 0)) {
            const float* Rcol = s_R + tid;
            float a0 = 0.f, a1 = 0.f, a2 = 0.f, a3 = 0.f;
#pragma unroll
            for (int uu = 0; uu < 56; uu += 4) {
                a0 += Rcol[(uu    ) * RMS];
                a1 += Rcol[(uu + 1) * RMS];
                a2 += Rcol[(uu + 2) * RMS];
                a3 += Rcol[(uu + 3) * RMS];
            }
            float acc = ((a0 + a2) + (a1 + a3)) + Rcol[56 * RMS];
            float* gc = g_corr + (size_t)bc * 4096;
            int m = b2;
            int n = di * 8 + (b2 + dj);
            gc[m * 64 + n] = acc;
            gc[n * 64 + m] = acc;
#pragma unroll
            for (int a = 1; a <= 7; ++a) {
                if (a <= 7 - di) {
                    acc += Rcol[(a + 56) * RMS] - Rcol[(a - 1) * RMS];
                    m = a * 8 + b2;
                    n = (a + di) * 8 + (b2 + dj);
                    gc[m * 64 + n] = acc;
                    gc[n * 64 + m] = acc;
                }
            }
        }
    }
}

// ---------------------------------------------------------------------------
// Stage 1b: one block per bc. Norms + warp-sort ranking -> pool (c-major).
// ---------------------------------------------------------------------------
__global__ __launch_bounds__(256) void s1b_kernel()
{
    __shared__ float s_corr[64 * CMS];
    __shared__ float s_norm[64];

    const int tid = threadIdx.x;
    const int bc  = blockIdx.x;
    const int bb  = bc >> 6;
    const int cc  = bc & 63;

    const float* src = g_corr + (size_t)bc * 4096;
    for (int i = tid; i < 4096; i += 256)
        s_corr[(i >> 6) * CMS + (i & 63)] = src[i];
    __syncthreads();

    if (tid < 64) {
        float gdiag = s_corr[tid * CMS + tid];
        s_norm[tid] = 1.0f / fmaxf(sqrtf(gdiag), 1e-12f);
    }
    __syncthreads();

    const int lane = tid & 31;
    const int w    = tid >> 5;
    float* dstc = g_pool2t + (size_t)(bb * 64 + cc) * POOL_P;
    const float invP = 1.0f / (float)NP;
    const float nm0 = s_norm[lane] * invP;
    const float nm1 = s_norm[lane + 32] * invP;

    float v0[8], v1[8];
#pragma unroll
    for (int ci = 0; ci < 8; ++ci) {
        const int n = w * 8 + ci;
        const float sn = s_norm[n];
        v0[ci] = s_corr[lane * CMS + n] * nm0 * sn;
        v1[ci] = s_corr[(lane + 32) * CMS + n] * nm1 * sn;
    }

#pragma unroll
    for (int s = 1; s <= 5; ++s) {
        const int kk = 1 << s;
#pragma unroll
        for (int j = (1 << (s - 1)); j >= 1; j >>= 1) {
#pragma unroll
            for (int ci = 0; ci < 8; ++ci) {
                const bool A = ((lane & j) == 0);
                bool d0, d1;
                if (s < 5) { d0 = ((lane & kk) == 0); d1 = d0; }
                else       { d0 = true; d1 = false; }
                float p0 = __shfl_xor_sync(0xffffffffu, v0[ci], j);
                v0[ci] = ((d0 == A) ? fmaxf(v0[ci], p0) : fminf(v0[ci], p0));
                float p1 = __shfl_xor_sync(0xffffffffu, v1[ci], j);
                v1[ci] = ((d1 == A) ? fmaxf(v1[ci], p1) : fminf(v1[ci], p1));
            }
        }
    }
#pragma unroll
    for (int ci = 0; ci < 8; ++ci) {
        float hi = fmaxf(v0[ci], v1[ci]);
        float lo = fminf(v0[ci], v1[ci]);
        v0[ci] = hi; v1[ci] = lo;
    }
#pragma unroll
    for (int j = 16; j >= 1; j >>= 1) {
#pragma unroll
        for (int ci = 0; ci < 8; ++ci) {
            const bool A = ((lane & j) == 0);
            float p0 = __shfl_xor_sync(0xffffffffu, v0[ci], j);
            v0[ci] = A ? fmaxf(v0[ci], p0) : fminf(v0[ci], p0);
            float p1 = __shfl_xor_sync(0xffffffffu, v1[ci], j);
            v1[ci] = A ? fmaxf(v1[ci], p1) : fminf(v1[ci], p1);
        }
    }

#pragma unroll
    for (int ci = 0; ci < 8; ++ci) {
        const int n = w * 8 + ci;
        if (lane == 1)  dstc[0 * 64 + n] = v0[ci];
        if (lane == 9)  dstc[1 * 64 + n] = v0[ci];
        if (lane == 16) dstc[2 * 64 + n] = v0[ci];
        if (lane == 24) dstc[3 * 64 + n] = v0[ci];
        if (lane == 0)  dstc[4 * 64 + n] = v1[ci];
        if (lane == 8)  dstc[5 * 64 + n] = v1[ci];
        if (lane == 16) dstc[6 * 64 + n] = v1[ci];
        if (lane == 23) dstc[7 * 64 + n] = v1[ci];
        if (lane == 31) dstc[8 * 64 + n] = v1[ci];
    }
}

// ---------------------------------------------------------------------------
// Sort primitives (r-major layout i = r*32 + lane, regs 0..17 all real).
// ---------------------------------------------------------------------------
__device__ __forceinline__ void sh(float& v, int j, bool keep_max) {
    float pv = __shfl_xor_sync(0xffffffffu, v, j);
    v = keep_max ? fmaxf(v, pv) : fminf(v, pv);
}
__device__ __forceinline__ void cx(float& a, float& b, bool dsc) {
    float x = a, y = b;
    a = dsc ? fmaxf(x, y) : fminf(x, y);
    b = dsc ? fminf(x, y) : fmaxf(x, y);
}

// ---------------------------------------------------------------------------
// Stage 2 (fused): one block per (b, 8 q). Dot phase computes per-p inverse
// norms inline; warp w sorts column q0+w with the dummy-free 576 network.
// ---------------------------------------------------------------------------
__global__ __launch_bounds__(256, 4) void stage2_kernel(float* __restrict__ out)
{
    __shared__ float4 s_xq4[8][16];          // 8 q vectors x 64 ch
    __shared__ float  s_cols[8][POOL_P];     // swizzled via ph()
    __shared__ float  s_ip[POOL_P];          // inverse norms

    const int tid  = threadIdx.x;
    const int lane = tid & 31;
    const int w    = tid >> 5;
    const int b    = blockIdx.x / 72;
    const int q0   = (blockIdx.x % 72) * 8;

    const float* poolb = g_pool2t + (size_t)b * 64 * POOL_P;

    {   // load 8 q vectors
        float* sx = (float*)s_xq4;
        for (int i = tid; i < 512; i += 256) {
            int k = i >> 6, c = i & 63;
            sx[k * 64 + c] = poolb[(size_t)c * POOL_P + (q0 + k)];
        }
    }
    __syncthreads();

    // ---- dot phase + inline norms -----------------------------------------
#pragma unroll
    for (int pi = 0; pi < 3; ++pi) {
        const int p = tid + pi * 256;
        if (p < POOL_P) {
            float d[8];
#pragma unroll
            for (int k = 0; k < 8; ++k) d[k] = 0.0f;
            float n0 = 0.f, n1 = 0.f, n2 = 0.f, n3 = 0.f;
#pragma unroll 4
            for (int c4 = 0; c4 < 16; ++c4) {
                const float* xb = poolb + (size_t)(c4 * 4) * POOL_P + p;
                float x0 = xb[0];
                float x1 = xb[POOL_P];
                float x2 = xb[2 * POOL_P];
                float x3 = xb[3 * POOL_P];
                n0 = fmaf(x0, x0, n0); n1 = fmaf(x1, x1, n1);
                n2 = fmaf(x2, x2, n2); n3 = fmaf(x3, x3, n3);
#pragma unroll
                for (int k = 0; k < 8; ++k) {
                    float4 q = s_xq4[k][c4];
                    d[k] = fmaf(x0, q.x, d[k]);
                    d[k] = fmaf(x1, q.y, d[k]);
                    d[k] = fmaf(x2, q.z, d[k]);
                    d[k] = fmaf(x3, q.w, d[k]);
                }
            }
            const float s = (n0 + n2) + (n1 + n3);
            const float ip = 1.0f / fmaxf(sqrtf(s), 1e-12f);
            s_ip[p] = ip;
            const int pp = ph(p);
#pragma unroll
            for (int k = 0; k < 8; ++k)
                s_cols[k][pp] = d[k] * ip;
        }
    }
    __syncthreads();

    // ---- dummy-free 576 bitonic sort, i = r*32 + lane (r = 0..17) ---------
    {
        float v[18];
#pragma unroll
        for (int r = 0; r < 18; ++r)
            v[r] = s_cols[w][r * 32 + ((lane ^ r) & 31)];

        // stages 1..4
#pragma unroll
        for (int s = 1; s <= 4; ++s) {
            const int kk = 1 << s;
#pragma unroll
            for (int j = kk >> 1; j >= 1; j >>= 1) {
                const bool km = (((lane & kk) == 0) == ((lane & j) == 0));
#pragma unroll
                for (int r = 0; r < 18; ++r) sh(v[r], j, km);
            }
        }
        // stage 5
#pragma unroll
        for (int j = 16; j >= 1; j >>= 1) {
            const bool A = (lane & j) == 0;
#pragma unroll
            for (int r = 0; r < 18; ++r) sh(v[r], j, ((r & 1) == 0) == A);
        }
        // stage 6
#pragma unroll
        for (int m = 0; m < 9; ++m) cx(v[2*m], v[2*m+1], (m & 1) == 0);
#pragma unroll
        for (int j = 16; j >= 1; j >>= 1) {
            const bool A = (lane & j) == 0;
#pragma unroll
            for (int r = 0; r < 18; ++r) sh(v[r], j, ((r & 2) == 0) == A);
        }
        // stage 7
#pragma unroll
        for (int g = 0; g < 4; ++g) {
            cx(v[4*g],   v[4*g+2], (g & 1) == 0);
            cx(v[4*g+1], v[4*g+3], (g & 1) == 0);
        }
#pragma unroll
        for (int m = 0; m < 9; ++m) cx(v[2*m], v[2*m+1], (m & 2) == 0);
#pragma unroll
        for (int j = 16; j >= 1; j >>= 1) {
            const bool A = (lane & j) == 0;
#pragma unroll
            for (int r = 0; r < 18; ++r) sh(v[r], j, ((r & 4) == 0) == A);
        }
        // stage 8
#pragma unroll
        for (int g = 0; g < 2; ++g)
#pragma unroll
            for (int t = 0; t < 4; ++t)
                cx(v[8*g + t], v[8*g + t + 4], g == 0);
#pragma unroll
        for (int g = 0; g < 4; ++g) {
            const bool d8 = ((4 * g) & 8) == 0;
            cx(v[4*g],   v[4*g+2], d8);
            cx(v[4*g+1], v[4*g+3], d8);
        }
#pragma unroll
        for (int m = 0; m < 9; ++m) cx(v[2*m], v[2*m+1], (m & 4) == 0);
#pragma unroll
        for (int j = 16; j >= 1; j >>= 1) {
            const bool A = (lane & j) == 0;
#pragma unroll
            for (int r = 0; r < 18; ++r) sh(v[r], j, ((r & 8) == 0) == A);
        }
        // stage 9
        float ua = __shfl_xor_sync(0xffffffffu, v[17], 31);   // role 30
        float ub = __shfl_xor_sync(0xffffffffu, v[16], 31);   // role 31
#pragma unroll
        for (int r = 0; r < 8; ++r) cx(v[r], v[r+8], true);
#pragma unroll
        for (int g = 0; g < 2; ++g)
#pragma unroll
            for (int t = 0; t < 4; ++t) cx(v[8*g+t], v[8*g+t+4], true);
#pragma unroll
        for (int g = 0; g < 4; ++g) { cx(v[4*g], v[4*g+2], true); cx(v[4*g+1], v[4*g+3], true); }
#pragma unroll
        for (int m = 0; m < 8; ++m) cx(v[2*m], v[2*m+1], true);
#pragma unroll
        for (int j = 16; j >= 1; j >>= 1) {
            const bool A = (lane & j) == 0;
#pragma unroll
            for (int r = 0; r < 16; ++r) sh(v[r], j, A);
        }
        // stage 10
        cx(v[14], ua, true);
        cx(v[15], ub, true);
#pragma unroll
        for (int r = 0; r < 8; ++r) cx(v[r], v[r+8], true);
#pragma unroll
        for (int g = 0; g < 2; ++g)
#pragma unroll
            for (int t = 0; t < 4; ++t) cx(v[8*g+t], v[8*g+t+4], true);
#pragma unroll
        for (int g = 0; g < 4; ++g) { cx(v[4*g], v[4*g+2], true); cx(v[4*g+1], v[4*g+3], true); }
#pragma unroll
        for (int m = 0; m < 8; ++m) cx(v[2*m], v[2*m+1], true);
#pragma unroll
        for (int j = 16; j >= 1; j >>= 1) {
            const bool A = (lane & j) == 0;
#pragma unroll
            for (int r = 0; r < 16; ++r) sh(v[r], j, A);
        }
        cx(ua, ub, true);
#pragma unroll
        for (int j = 16; j >= 1; j >>= 1) {
            const bool A = (lane & j) == 0;
            sh(ua, j, A);
            sh(ub, j, A);
        }
        v[16] = ua; v[17] = ub;

#pragma unroll
        for (int r = 0; r < 18; ++r)
            s_cols[w][r * 32 + ((lane ^ r) & 31)] = v[r];
    }
    __syncthreads();

    const double step = 574.0 / 114.0;   // np.linspace(1, 575, 115) step
    for (int idx = tid; idx < 8 * OUT_R; idx += 256) {
        int k = idx & 7, rr = idx >> 3;
        int rank = (int)rint(1.0 + (double)rr * step);  // half-even == np.round
        float invq = s_ip[q0 + k];
        out[((size_t)b * OUT_R + rr) * POOL_P + (q0 + k)] =
            s_cols[k][ph(rank)] * invq * (1.0f / 64.0f);
    }
}

// ---------------------------------------------------------------------------
extern "C" void kernel_launch(void* const* d_in, const int* in_sizes, int n_in,
                              void* d_out, int out_size)
{
    const float* x = (const float*)d_in[0];
    float* out = (float*)d_out;

    s1a_kernel<<<512 * 8, 128, S1A_SMEM_BYTES>>>(x);
    s1b_kernel<<<512, 256>>>();
    stage2_kernel<<<8 * 72, 256>>>(out);
}